// round 13
// baseline (speedup 1.0000x reference)
#include <cuda_runtime.h>
#include <cuda_fp16.h>
#include <math.h>
#include <stdint.h>

#define NB 8192
#define NT 21
#define NF 3
#define NU 512
#define NZ 2048

#define KCH 32                    // K per chunk
#define SROW 40                   // smem halves per row (80B, 20 banks -> conflict-free)
#define TILE_B (128 * SROW * 2)   // 10240 B per operand tile
#define STAGE_B (4 * TILE_B)      // Ah/Al/Bh/Bl = 40960 B
#define EPI_OFF (2 * STAGE_B)     // 81920
#define ROWS_OFF (EPI_OFF + 2048) // 83968: int[128] compacted row ids
#define SM_DYN (ROWS_OFF + 640)

#define NRNN 256                  // RNN blocks scheduled first (longest-first)

// ---------------- persistent scratch --------------------------------------
__device__ float  g_c  [NB * NU];
__device__ float  g_tc [NB * NU];
__device__ float  g_oc [NB * NU];
__device__ float  g_hrf[NB * NU];
__device__ __half g_hah[2][NB * NU];   // LSTM h fp16 hi, ping-pong by step parity
__device__ __half g_hal[2][NB * NU];   // LSTM h fp16 lo
__device__ __half g_hph[2][NB * NU];   // RNN state hi ping-pong
__device__ __half g_hpl[2][NB * NU];   // RNN state lo ping-pong
__device__ __half g_BLh[NZ * NU];      // permuted lstm weights [n=u*4+g][k] hi
__device__ __half g_BLl[NZ * NU];      // lo
__device__ __half g_BRh[NU * 1024];    // rnn concat [n][k: Wr|Ur] hi
__device__ __half g_BRl[NU * 1024];    // lo
__device__ float4 g_Wkp4[NZ];          // (Wk[0][n],Wk[1][n],Wk[2][n],bias[n]) permuted
__device__ int    g_oidx[NT * NB];
__device__ int    g_rows[NT * NB];     // compacted learned-row ids (padded w/ -1)
__device__ int    g_urows[NT * NB];    // compacted UNlearned row ids
__device__ int    g_cnt [NT];
__device__ int    g_ucnt[NT];
__device__ unsigned char g_m[NT * NB];
__device__ float  g_weff[NU];
__device__ float  g_beff;

// ---------------- helpers ---------------------------------------------------
__device__ __forceinline__ uint32_t smem_u32(const void* p) {
    uint32_t a;
    asm("{ .reg .u64 t; cvta.to.shared.u64 t, %1; cvt.u32.u64 %0, t; }" : "=r"(a) : "l"(p));
    return a;
}
__device__ __forceinline__ void cpasync16(uint32_t dst, const void* src) {
    asm volatile("cp.async.ca.shared.global [%0], [%1], 16;" :: "r"(dst), "l"(src));
}
#define CP_COMMIT() asm volatile("cp.async.commit_group;" ::: "memory")
#define CP_WAIT(n)  asm volatile("cp.async.wait_group %0;" :: "n"(n) : "memory")

#define LDSM4(r0, r1, r2, r3, addr) \
    asm volatile("ldmatrix.sync.aligned.m8n8.x4.shared.b16 {%0,%1,%2,%3}, [%4];" \
        : "=r"(r0), "=r"(r1), "=r"(r2), "=r"(r3) : "r"(addr))

__device__ __forceinline__ void mma16816(float* c, const uint32_t* a, uint32_t b0, uint32_t b1) {
    asm volatile(
        "mma.sync.aligned.m16n8k16.row.col.f32.f16.f16.f32 "
        "{%0,%1,%2,%3}, {%4,%5,%6,%7}, {%8,%9}, {%0,%1,%2,%3};"
        : "+f"(c[0]), "+f"(c[1]), "+f"(c[2]), "+f"(c[3])
        : "r"(a[0]), "r"(a[1]), "r"(a[2]), "r"(a[3]), "r"(b0), "r"(b1));
}
__device__ __forceinline__ float sigf(float z) {
    float e = __expf(-z);
    return __fdividef(1.f, 1.f + e);
}
__device__ __forceinline__ float tanhfast(float z) {
    float e = __expf(fminf(2.f * z, 80.f));
    return __fdividef(e - 1.f, e + 1.f);
}
__device__ __forceinline__ void split16(float f, __half& h, __half& l) {
    h = __float2half_rn(f);
    l = __float2half_rn(f - __half2float(h));
}

// ---------------- mask + cummax gather index + row compaction ----------------
__global__ void k_oidx(const int* __restrict__ learn) {
    int t = blockIdx.x;
    int tid = threadIdx.x;
    __shared__ int s_any, s_first;
    __shared__ int s_scan[1024];
    if (tid == 0) { s_any = 0; s_first = 0x7fffffff; }
    __syncthreads();
    int base = tid * 8;
    int m[8]; int la = 0;
#pragma unroll
    for (int j = 0; j < 8; j++) { m[j] = (learn[t * NB + base + j] == 1) ? 1 : 0; la |= m[j]; }
    if (la) atomicOr(&s_any, 1);
    __syncthreads();
    if (tid == 0 && !s_any) m[0] = 1;
    int lf = 0x7fffffff;
#pragma unroll
    for (int j = 0; j < 8; j++) if (m[j] && lf == 0x7fffffff) lf = base + j;
    if (lf != 0x7fffffff) atomicMin(&s_first, lf);

    // cummax scan (for o-gather indices)
    int run = -1; int lv[8];
#pragma unroll
    for (int j = 0; j < 8; j++) { if (m[j]) run = base + j; lv[j] = run; }
    s_scan[tid] = run;
    __syncthreads();
    for (int off = 1; off < 1024; off <<= 1) {
        int other = (tid >= off) ? s_scan[tid - off] : -1;
        __syncthreads();
        if (other > s_scan[tid]) s_scan[tid] = other;
        __syncthreads();
    }
    int prefix = (tid > 0) ? s_scan[tid - 1] : -1;
    int first = s_first;
#pragma unroll
    for (int j = 0; j < 8; j++) {
        int v = (lv[j] >= 0) ? lv[j] : prefix;
        g_oidx[t * NB + base + j] = (v < 0) ? first : v;
        g_m[t * NB + base + j] = (unsigned char)m[j];
    }
    __syncthreads();

    // prefix-sum -> learned list (g_rows) and unlearned list (g_urows)
    int lc = 0;
#pragma unroll
    for (int j = 0; j < 8; j++) lc += m[j];
    s_scan[tid] = lc;
    __syncthreads();
    for (int off = 1; off < 1024; off <<= 1) {
        int other = (tid >= off) ? s_scan[tid - off] : 0;
        __syncthreads();
        s_scan[tid] += other;
        __syncthreads();
    }
    int lpos = s_scan[tid] - lc;        // learned before my first element
    int cnt = s_scan[1023];
#pragma unroll
    for (int j = 0; j < 8; j++) {
        int gi = base + j;
        if (m[j]) g_rows[t * NB + lpos++] = gi;
        else      g_urows[t * NB + (gi - lpos)] = gi;
    }
    int padded = (cnt + 127) & ~127;
    int pidx = cnt + tid;
    if (pidx < padded) g_rows[t * NB + pidx] = -1;
    if (tid == 0) { g_cnt[t] = cnt; g_ucnt[t] = NB - cnt; }
}

// ---------------- weight conversion (once per launch) -----------------------
__global__ void k_convRk(const float* __restrict__ Rk) {
    int idx = blockIdx.x * 256 + threadIdx.x;     // NZ*NU
    int k = idx & 511, n = idx >> 9;
    float v = Rk[(size_t)k * NZ + (n & 3) * NU + (n >> 2)];
    __half h, l; split16(v, h, l);
    g_BLh[idx] = h; g_BLl[idx] = l;
}
__global__ void k_convWU(const float* __restrict__ Wr, const float* __restrict__ Ur) {
    int idx = blockIdx.x * 256 + threadIdx.x;     // NU*1024
    int k = idx & 1023, n = idx >> 10;
    float v = (k < 512) ? Wr[(size_t)k * NU + n] : Ur[(size_t)(k - 512) * NU + n];
    __half h, l; split16(v, h, l);
    g_BRh[idx] = h; g_BRl[idx] = l;
}
__global__ void k_convWkp(const float* __restrict__ Wk, const float* __restrict__ bias) {
    int n = blockIdx.x * 256 + threadIdx.x;       // NZ
    int col = (n & 3) * NU + (n >> 2);
    g_Wkp4[n] = make_float4(Wk[col], Wk[NZ + col], Wk[2 * NZ + col], bias[col]);
}

// ---------------- LSTM t=0 (h=0 -> no GEMM); writes h(0) for ALL rows -------
// (unlearned rows: c=0 -> tc=0 -> h=0, so oc[oidx]*tc = 0 without the gather)
__global__ void k_lstm0s(const float* __restrict__ x) {
    int idx = blockIdx.x * 256 + threadIdx.x;     // NB*NU
    int row = idx >> 9, u = idx & 511;
    float x0 = x[row * (NT * NF) + 0];
    float x1 = x[row * (NT * NF) + 1];
    float x2 = x[row * (NT * NF) + 2];
    float4 w0 = g_Wkp4[u * 4 + 0];
    float4 w2 = g_Wkp4[u * 4 + 2];
    float4 w3 = g_Wkp4[u * 4 + 3];
    float zi = x0 * w0.x + x1 * w0.y + x2 * w0.z + w0.w;
    float zg = x0 * w2.x + x1 * w2.y + x2 * w2.z + w2.w;
    float zo = x0 * w3.x + x1 * w3.y + x2 * w3.z + w3.w;
    bool mk = g_m[row] != 0;
    float c = mk ? sigf(zi) * tanhfast(zg) : 0.f;
    float tcv = tanhfast(c);
    float og = sigf(zo);
    g_c[idx] = c;
    g_tc[idx] = tcv;
    g_oc[idx] = og;
    float hv = og * tcv;                // == 0 for unlearned rows
    __half hh, hl; split16(hv, hh, hl);
    g_hah[0][idx] = hh;
    g_hal[0][idx] = hl;
}

// ---------------- gather (UNLEARNED rows only): h = oc[oidx]*tc -------------
__global__ void k_gatherU(int t, int hb) {
    int ucnt = g_ucnt[t];
    int total = ucnt * 64;
    __half* dh = g_hah[hb];
    __half* dl = g_hal[hb];
    for (int i = blockIdx.x * 256 + threadIdx.x; i < total; i += gridDim.x * 256) {
        int r = i >> 6, q = i & 63;
        int b = g_urows[t * NB + r];
        int src = g_oidx[t * NB + b];
        const float4* po = (const float4*)(g_oc + (size_t)src * NU) + q * 2;
        const float4* pt = (const float4*)(g_tc + (size_t)b * NU) + q * 2;
        float4 o0 = po[0], o1 = po[1], t0 = pt[0], t1 = pt[1];
        float h[8] = {o0.x*t0.x, o0.y*t0.y, o0.z*t0.z, o0.w*t0.w,
                      o1.x*t1.x, o1.y*t1.y, o1.z*t1.z, o1.w*t1.w};
        uint32_t hw[4], lw[4];
#pragma unroll
        for (int p = 0; p < 4; p++) {
            __half h0, l0, h1, l1;
            split16(h[p*2], h0, l0); split16(h[p*2+1], h1, l1);
            __half2 hh = __halves2half2(h0, h1);
            __half2 ll = __halves2half2(l0, l1);
            hw[p] = *(uint32_t*)&hh; lw[p] = *(uint32_t*)&ll;
        }
        size_t o = (size_t)b * 64 + q;
        ((uint4*)dh)[o] = make_uint4(hw[0], hw[1], hw[2], hw[3]);
        ((uint4*)dl)[o] = make_uint4(lw[0], lw[1], lw[2], lw[3]);
    }
}

// ---------------- fused HMMA GEMM kernel ------------------------------------
// blocks [0, NRNN): RNN step tR (longest-first).
// blocks [NRNN, ..): LSTM step tL on compacted learned rows; epilogue ALSO
// writes h(tL) for its rows into the hpar^1 buffer (learned-row gather fold).
__global__ void __launch_bounds__(256, 2) k_hmma(
    const float* __restrict__ x, const float* __restrict__ br,
    int tL, int tR, int par, int hpar)
{
    extern __shared__ char smraw[];
    const uint32_t sb = smem_u32(smraw);
    const int tid = threadIdx.x;
    const int w = tid >> 5, lane = tid & 31;
    const int wm = w & 3, wn = w >> 2;

    const bool isL = (int)blockIdx.x >= NRNN;
    int m0, n0, nch, t, ldb;
    const __half *Bh, *Bl;
    const __half *A2h = nullptr, *A2l = nullptr;
    int* srows = (int*)(smraw + ROWS_OFF);
    const __half* Hh = g_hah[hpar];     // h(tR) consumed this launch
    const __half* Hl = g_hal[hpar];

    if (isL) {
        int b = blockIdx.x - NRNN;
        n0 = (b & 15) * 128;
        int mtile = b >> 4;
        int cnt = g_cnt[tL];
        if (mtile * 128 >= cnt) return;           // uniform early-exit
        m0 = mtile * 128;
        nch = 16; t = tL; Bh = g_BLh; Bl = g_BLl; ldb = 512;
        if (tid < 128) srows[tid] = g_rows[tL * NB + m0 + tid];
    } else {
        int r = blockIdx.x;
        n0 = (r & 3) * 128; m0 = (r >> 2) * 128;
        nch = (tR == 0) ? 16 : 32; t = tR; Bh = g_BRh; Bl = g_BRl; ldb = 1024;
        A2h = g_hph[par]; A2l = g_hpl[par];
    }

    float4* sWkp = (float4*)(smraw + EPI_OFF);
    float*  sbr  = (float*)(smraw + EPI_OFF);
    if (isL) { if (tid < 128) sWkp[tid] = g_Wkp4[n0 + tid]; }
    else     { if (tid < 128) sbr[tid]  = br[n0 + tid]; }
    __syncthreads();

    float acc[2][8][4];
#pragma unroll
    for (int i = 0; i < 2; i++)
#pragma unroll
        for (int j = 0; j < 8; j++)
#pragma unroll
            for (int q = 0; q < 4; q++) acc[i][j][q] = 0.f;

    auto load_chunk = [&](int c, int s) {
        const __half *Ah, *Al; int kc;
        if (isL || c < 16) { Ah = Hh;  Al = Hl;  kc = c * KCH; }
        else               { Ah = A2h; Al = A2l; kc = (c - 16) * KCH; }
        const int kb = c * KCH;
        const uint32_t st = sb + s * STAGE_B;
#pragma unroll
        for (int q = 0; q < 2; q++) {
            int i = tid + q * 256;
            int row = i >> 2, seg = i & 3;
            uint32_t so = row * (SROW * 2) + seg * 16;
            size_t ar;
            if (isL) { int rid = srows[row]; ar = (size_t)(rid < 0 ? 0 : rid); }
            else     { ar = (size_t)(m0 + row); }
            cpasync16(st +              so, Ah + ar * 512 + kc + seg * 8);
            cpasync16(st +     TILE_B + so, Al + ar * 512 + kc + seg * 8);
            cpasync16(st + 2 * TILE_B + so, Bh + (size_t)(n0 + row) * ldb + kb + seg * 8);
            cpasync16(st + 3 * TILE_B + so, Bl + (size_t)(n0 + row) * ldb + kb + seg * 8);
        }
    };

    const uint32_t arow = (lane & 15) * (SROW * 2) + ((lane >> 4) << 4);

    auto compute_chunk = [&](int s) {
        const uint32_t st = sb + s * STAGE_B;
#pragma unroll
        for (int ks = 0; ks < 2; ks++) {
            const uint32_t ko = ks * 32;
            uint32_t ah[2][4], al[2][4];
#pragma unroll
            for (int mt = 0; mt < 2; mt++) {
                uint32_t aoff = (wm * 32 + mt * 16) * (SROW * 2) + arow + ko;
                LDSM4(ah[mt][0], ah[mt][1], ah[mt][2], ah[mt][3], st + aoff);
                LDSM4(al[mt][0], al[mt][1], al[mt][2], al[mt][3], st + TILE_B + aoff);
            }
#pragma unroll
            for (int np = 0; np < 4; np++) {
                uint32_t bo = (wn * 64 + np * 16) * (SROW * 2) + arow + ko;
                uint32_t bh[4], bl[4];
                LDSM4(bh[0], bh[1], bh[2], bh[3], st + 2 * TILE_B + bo);
                LDSM4(bl[0], bl[1], bl[2], bl[3], st + 3 * TILE_B + bo);
#pragma unroll
                for (int mt = 0; mt < 2; mt++) {
                    float* ce = acc[mt][np * 2];
                    float* co = acc[mt][np * 2 + 1];
                    mma16816(ce, ah[mt], bh[0], bh[2]);
                    mma16816(ce, ah[mt], bl[0], bl[2]);
                    mma16816(ce, al[mt], bh[0], bh[2]);
                    mma16816(co, ah[mt], bh[1], bh[3]);
                    mma16816(co, ah[mt], bl[1], bl[3]);
                    mma16816(co, al[mt], bh[1], bh[3]);
                }
            }
        }
    };

    load_chunk(0, 0); CP_COMMIT();
    for (int c = 0; c < nch; c++) {
        if (c + 1 < nch) { load_chunk(c + 1, (c + 1) & 1); CP_COMMIT(); CP_WAIT(1); }
        else             { CP_WAIT(0); }
        __syncthreads();
        compute_chunk(c & 1);
        __syncthreads();
    }

    // ---- epilogue ----
    const int grow = lane >> 2, tig = lane & 3;
    const bool evn = (tig & 1) == 0;

    if (isL) {
        __half* nHh = g_hah[hpar ^ 1];  // h(tL) output buffer
        __half* nHl = g_hal[hpar ^ 1];
        float xs[2][3]; int rid[2]; bool val[2];
#pragma unroll
        for (int mt = 0; mt < 2; mt++) {
            int local = wm * 32 + mt * 16 + grow + (evn ? 0 : 8);
            rid[mt] = srows[local];
            val[mt] = rid[mt] >= 0;
            const float* xp = x + (size_t)(val[mt] ? rid[mt] : 0) * (NT * NF) + t * NF;
            xs[mt][0] = xp[0]; xs[mt][1] = xp[1]; xs[mt][2] = xp[2];
        }
#pragma unroll
        for (int mt = 0; mt < 2; mt++) {
#pragma unroll
            for (int nt = 0; nt < 8; nt++) {
                float* c = acc[mt][nt];
                float p0 = __shfl_xor_sync(0xffffffffu, c[0], 1);
                float p1 = __shfl_xor_sync(0xffffffffu, c[1], 1);
                float p2 = __shfl_xor_sync(0xffffffffu, c[2], 1);
                float p3 = __shfl_xor_sync(0xffffffffu, c[3], 1);
                float zi, zf, zg, zo;
                if (evn) { zi = c[0]; zf = c[1]; zg = p0; zo = p1; }
                else     { zi = p2; zf = p3; zg = c[2]; zo = c[3]; }
                if (!val[mt]) continue;
                int u_loc = wn * 16 + nt * 2 + (tig >> 1);
                float4 w0 = sWkp[u_loc * 4 + 0];
                float4 w1 = sWkp[u_loc * 4 + 1];
                float4 w2 = sWkp[u_loc * 4 + 2];
                float4 w3 = sWkp[u_loc * 4 + 3];
                zi += xs[mt][0]*w0.x + xs[mt][1]*w0.y + xs[mt][2]*w0.z + w0.w;
                zf += xs[mt][0]*w1.x + xs[mt][1]*w1.y + xs[mt][2]*w1.z + w1.w;
                zg += xs[mt][0]*w2.x + xs[mt][1]*w2.y + xs[mt][2]*w2.z + w2.w;
                zo += xs[mt][0]*w3.x + xs[mt][1]*w3.y + xs[mt][2]*w3.z + w3.w;
                int u = (n0 >> 2) + u_loc;
                size_t off = (size_t)rid[mt] * NU + u;
                float ig = sigf(zi), fg = sigf(zf), gg = tanhfast(zg), og = sigf(zo);
                float cold = g_c[off];
                float cn = fmaf(fg, cold, ig * gg);
                float tcv = tanhfast(cn);
                g_c[off]  = cn;
                g_tc[off] = tcv;
                g_oc[off] = og;
                // learned row: oidx == self, so h = og * tcv (gather fold)
                float hv = og * tcv;
                __half hh, hl; split16(hv, hh, hl);
                nHh[off] = hh;
                nHl[off] = hl;
            }
        }
    } else {
        __half* dh = g_hph[par ^ 1];
        __half* dl = g_hpl[par ^ 1];
        const bool last = (tR == 20);
#pragma unroll
        for (int mt = 0; mt < 2; mt++) {
            int r0 = m0 + wm * 32 + mt * 16 + grow;
#pragma unroll
            for (int nt = 0; nt < 8; nt++) {
                float* c = acc[mt][nt];
                int ncl = wn * 64 + nt * 8 + tig * 2;
                int nc = n0 + ncl;
                float b0 = sbr[ncl], b1 = sbr[ncl + 1];
                float v00 = tanhfast(c[0] + b0), v01 = tanhfast(c[1] + b1);
                float v10 = tanhfast(c[2] + b0), v11 = tanhfast(c[3] + b1);
                if (last) {
                    *(float2*)&g_hrf[(size_t)r0 * NU + nc]       = make_float2(v00, v01);
                    *(float2*)&g_hrf[(size_t)(r0 + 8) * NU + nc] = make_float2(v10, v11);
                } else {
                    __half h0, l0, h1, l1;
                    split16(v00, h0, l0); split16(v01, h1, l1);
                    *(__half2*)&dh[(size_t)r0 * NU + nc] = __halves2half2(h0, h1);
                    *(__half2*)&dl[(size_t)r0 * NU + nc] = __halves2half2(l0, l1);
                    split16(v10, h0, l0); split16(v11, h1, l1);
                    *(__half2*)&dh[(size_t)(r0 + 8) * NU + nc] = __halves2half2(h0, h1);
                    *(__half2*)&dl[(size_t)(r0 + 8) * NU + nc] = __halves2half2(l0, l1);
                }
            }
        }
    }
}

// ---------------- fold FC + final projection --------------------------------
__global__ void k_weff(const float* __restrict__ wfc, const float* __restrict__ bfc,
                       const float* __restrict__ wout, const float* __restrict__ bout)
{
    int k = threadIdx.x;
    float s = 0.f;
#pragma unroll 8
    for (int j = 0; j < 32; j++) s += wfc[k * 32 + j] * wout[j];
    g_weff[k] = s;
    if (k == 0) {
        float b = bout[0];
        for (int j = 0; j < 32; j++) b += bfc[j] * wout[j];
        g_beff = b;
    }
}
__global__ void k_out(float* __restrict__ out) {
    int w = (blockIdx.x * blockDim.x + threadIdx.x) >> 5;
    int lane = threadIdx.x & 31;
    const float* h = g_hrf + (size_t)w * NU;
    float s = 0.f;
#pragma unroll
    for (int q = 0; q < 16; q++) s = fmaf(h[lane + q * 32], g_weff[lane + q * 32], s);
#pragma unroll
    for (int off = 16; off > 0; off >>= 1) s += __shfl_xor_sync(0xffffffffu, s, off);
    if (lane == 0) out[w] = s + g_beff;
}

// ---------------- launcher ---------------------------------------------------
extern "C" void kernel_launch(void* const* d_in, const int* in_sizes, int n_in,
                              void* d_out, int out_size)
{
    const float* x     = (const float*)d_in[0];
    const int*   learn = (const int*)  d_in[1];
    const float* Wk    = (const float*)d_in[2];
    const float* Rk    = (const float*)d_in[3];
    const float* bias  = (const float*)d_in[4];
    const float* Wr    = (const float*)d_in[5];
    const float* Ur    = (const float*)d_in[6];
    const float* br    = (const float*)d_in[7];
    const float* wfc   = (const float*)d_in[8];
    const float* bfc   = (const float*)d_in[9];
    const float* wout  = (const float*)d_in[10];
    const float* bout  = (const float*)d_in[11];
    float* out = (float*)d_out;

    cudaFuncSetAttribute(k_hmma, cudaFuncAttributeMaxDynamicSharedMemorySize, SM_DYN);

    k_oidx<<<NT, 1024>>>(learn);
    k_weff<<<1, 512>>>(wfc, bfc, wout, bout);
    k_convRk<<<(NZ * NU) / 256, 256>>>(Rk);
    k_convWU<<<(NU * 1024) / 256, 256>>>(Wr, Ur);
    k_convWkp<<<NZ / 256, 256>>>(Wk, bias);

    // t=0 LSTM: writes oc/tc/c AND h(0) for all rows (no gather(0) needed)
    k_lstm0s<<<(NB * NU) / 256, 256>>>(x);

    for (int t = 0; t < 20; t++) {
        // RNN(t) + LSTM(t+1); h(t) in buffer t&1, LSTM writes h(t+1) -> (t+1)&1
        k_hmma<<<NRNN + 1024, 256, SM_DYN>>>(x, br, t + 1, t, t & 1, t & 1);
        // unlearned rows of step t+1 (learned rows already written by epilogue)
        k_gatherU<<<64, 256>>>(t + 1, (t + 1) & 1);
    }
    // final RNN t=20 (rnn state parity: hph[0]; h(20) in buffer 20&1=0)
    k_hmma<<<NRNN, 256, SM_DYN>>>(x, br, -1, 20, 0, 0);
    k_out<<<NB / 8, 256>>>(out);
}

// round 15
// speedup vs baseline: 1.0211x; 1.0211x over previous
#include <cuda_runtime.h>
#include <cuda_fp16.h>
#include <math.h>
#include <stdint.h>

#define NB 8192
#define NT 21
#define NF 3
#define NU 512
#define NZ 2048

#define KCH 32                    // K per chunk
#define SROW 40                   // smem halves per row (80B, 20 banks -> conflict-free)
#define TILE_B (128 * SROW * 2)   // 10240 B per operand tile
#define STAGE_B (4 * TILE_B)      // Ah/Al/Bh/Bl = 40960 B
#define EPI_OFF (2 * STAGE_B)     // 81920
#define ROWS_OFF (EPI_OFF + 2048) // 83968: int[128] compacted row ids
#define SM_DYN (ROWS_OFF + 640)

#define NG 64                     // gather blocks inside k_grnn

// ---------------- persistent scratch --------------------------------------
__device__ float  g_c  [NB * NU];
__device__ float  g_tc [NB * NU];
__device__ float  g_oc [NB * NU];
__device__ float  g_hrf[NB * NU];
__device__ __half g_hah[2][NB * NU];   // LSTM h fp16 hi, ping-pong by step parity
__device__ __half g_hal[2][NB * NU];   // LSTM h fp16 lo
__device__ __half g_hph[2][NB * NU];   // RNN state hi ping-pong
__device__ __half g_hpl[2][NB * NU];   // RNN state lo ping-pong
__device__ __half g_BLh[NZ * NU];      // permuted lstm weights [n=u*4+g][k] hi
__device__ __half g_BLl[NZ * NU];      // lo
__device__ __half g_BRh[NU * 1024];    // rnn concat [n][k: Wr|Ur] hi
__device__ __half g_BRl[NU * 1024];    // lo
__device__ float4 g_Wkp4[NZ];          // (Wk[0][n],Wk[1][n],Wk[2][n],bias[n]) permuted
__device__ int    g_oidx[NT * NB];
__device__ int    g_rows[NT * NB];     // compacted learned-row ids (padded w/ -1)
__device__ int    g_cnt [NT];
__device__ unsigned char g_m[NT * NB];
__device__ float  g_weff[NU];
__device__ float  g_beff;

// ---------------- helpers ---------------------------------------------------
__device__ __forceinline__ uint32_t smem_u32(const void* p) {
    uint32_t a;
    asm("{ .reg .u64 t; cvta.to.shared.u64 t, %1; cvt.u32.u64 %0, t; }" : "=r"(a) : "l"(p));
    return a;
}
__device__ __forceinline__ void cpasync16(uint32_t dst, const void* src) {
    asm volatile("cp.async.ca.shared.global [%0], [%1], 16;" :: "r"(dst), "l"(src));
}
#define CP_COMMIT() asm volatile("cp.async.commit_group;" ::: "memory")
#define CP_WAIT(n)  asm volatile("cp.async.wait_group %0;" :: "n"(n) : "memory")

#define LDSM4(r0, r1, r2, r3, addr) \
    asm volatile("ldmatrix.sync.aligned.m8n8.x4.shared.b16 {%0,%1,%2,%3}, [%4];" \
        : "=r"(r0), "=r"(r1), "=r"(r2), "=r"(r3) : "r"(addr))

__device__ __forceinline__ void mma16816(float* c, const uint32_t* a, uint32_t b0, uint32_t b1) {
    asm volatile(
        "mma.sync.aligned.m16n8k16.row.col.f32.f16.f16.f32 "
        "{%0,%1,%2,%3}, {%4,%5,%6,%7}, {%8,%9}, {%0,%1,%2,%3};"
        : "+f"(c[0]), "+f"(c[1]), "+f"(c[2]), "+f"(c[3])
        : "r"(a[0]), "r"(a[1]), "r"(a[2]), "r"(a[3]), "r"(b0), "r"(b1));
}
__device__ __forceinline__ float sigf(float z) {
    float e = __expf(-z);
    return __fdividef(1.f, 1.f + e);
}
__device__ __forceinline__ float tanhfast(float z) {
    float e = __expf(fminf(2.f * z, 80.f));
    return __fdividef(e - 1.f, e + 1.f);
}
__device__ __forceinline__ void split16(float f, __half& h, __half& l) {
    h = __float2half_rn(f);
    l = __float2half_rn(f - __half2float(h));
}

// ---------------- mask + cummax gather index + learned-row compaction -------
__global__ void k_oidx(const int* __restrict__ learn) {
    int t = blockIdx.x;
    int tid = threadIdx.x;
    __shared__ int s_any, s_first;
    __shared__ int s_scan[1024];
    if (tid == 0) { s_any = 0; s_first = 0x7fffffff; }
    __syncthreads();
    int base = tid * 8;
    int m[8]; int la = 0;
#pragma unroll
    for (int j = 0; j < 8; j++) { m[j] = (learn[t * NB + base + j] == 1) ? 1 : 0; la |= m[j]; }
    if (la) atomicOr(&s_any, 1);
    __syncthreads();
    if (tid == 0 && !s_any) m[0] = 1;
    int lf = 0x7fffffff;
#pragma unroll
    for (int j = 0; j < 8; j++) if (m[j] && lf == 0x7fffffff) lf = base + j;
    if (lf != 0x7fffffff) atomicMin(&s_first, lf);

    int run = -1; int lv[8];
#pragma unroll
    for (int j = 0; j < 8; j++) { if (m[j]) run = base + j; lv[j] = run; }
    s_scan[tid] = run;
    __syncthreads();
    for (int off = 1; off < 1024; off <<= 1) {
        int other = (tid >= off) ? s_scan[tid - off] : -1;
        __syncthreads();
        if (other > s_scan[tid]) s_scan[tid] = other;
        __syncthreads();
    }
    int prefix = (tid > 0) ? s_scan[tid - 1] : -1;
    int first = s_first;
#pragma unroll
    for (int j = 0; j < 8; j++) {
        int v = (lv[j] >= 0) ? lv[j] : prefix;
        g_oidx[t * NB + base + j] = (v < 0) ? first : v;
        g_m[t * NB + base + j] = (unsigned char)m[j];
    }
    __syncthreads();

    int lc = 0;
#pragma unroll
    for (int j = 0; j < 8; j++) lc += m[j];
    s_scan[tid] = lc;
    __syncthreads();
    for (int off = 1; off < 1024; off <<= 1) {
        int other = (tid >= off) ? s_scan[tid - off] : 0;
        __syncthreads();
        s_scan[tid] += other;
        __syncthreads();
    }
    int pos = s_scan[tid] - lc;
    int cnt = s_scan[1023];
#pragma unroll
    for (int j = 0; j < 8; j++) {
        if (m[j]) g_rows[t * NB + pos++] = base + j;
    }
    int padded = (cnt + 127) & ~127;
    int pidx = cnt + tid;
    if (pidx < padded) g_rows[t * NB + pidx] = -1;
    if (tid == 0) g_cnt[t] = cnt;
}

// ---------------- weight conversion (once per launch) -----------------------
__global__ void k_convRk(const float* __restrict__ Rk) {
    int idx = blockIdx.x * 256 + threadIdx.x;     // NZ*NU
    int k = idx & 511, n = idx >> 9;
    float v = Rk[(size_t)k * NZ + (n & 3) * NU + (n >> 2)];
    __half h, l; split16(v, h, l);
    g_BLh[idx] = h; g_BLl[idx] = l;
}
__global__ void k_convWU(const float* __restrict__ Wr, const float* __restrict__ Ur) {
    int idx = blockIdx.x * 256 + threadIdx.x;     // NU*1024
    int k = idx & 1023, n = idx >> 10;
    float v = (k < 512) ? Wr[(size_t)k * NU + n] : Ur[(size_t)(k - 512) * NU + n];
    __half h, l; split16(v, h, l);
    g_BRh[idx] = h; g_BRl[idx] = l;
}
__global__ void k_convWkp(const float* __restrict__ Wk, const float* __restrict__ bias) {
    int n = blockIdx.x * 256 + threadIdx.x;       // NZ
    int col = (n & 3) * NU + (n >> 2);
    g_Wkp4[n] = make_float4(Wk[col], Wk[NZ + col], Wk[2 * NZ + col], bias[col]);
}

// ---------------- LSTM t=0 (h=0 -> no GEMM); also writes h(0), all rows -----
__global__ void k_lstm0s(const float* __restrict__ x) {
    int idx = blockIdx.x * 256 + threadIdx.x;     // NB*NU
    int row = idx >> 9, u = idx & 511;
    float x0 = x[row * (NT * NF) + 0];
    float x1 = x[row * (NT * NF) + 1];
    float x2 = x[row * (NT * NF) + 2];
    float4 w0 = g_Wkp4[u * 4 + 0];
    float4 w2 = g_Wkp4[u * 4 + 2];
    float4 w3 = g_Wkp4[u * 4 + 3];
    float zi = x0 * w0.x + x1 * w0.y + x2 * w0.z + w0.w;
    float zg = x0 * w2.x + x1 * w2.y + x2 * w2.z + w2.w;
    float zo = x0 * w3.x + x1 * w3.y + x2 * w3.z + w3.w;
    bool mk = g_m[row] != 0;
    float c = mk ? sigf(zi) * tanhfast(zg) : 0.f;
    float tcv = tanhfast(c);
    float og = sigf(zo);
    g_c[idx] = c;
    g_tc[idx] = tcv;
    g_oc[idx] = og;
    float hv = og * tcv;                // unlearned rows: tcv==0 -> hv==0 == gather result
    __half hh, hl; split16(hv, hh, hl);
    g_hah[0][idx] = hh;
    g_hal[0][idx] = hl;
}

// ---------------- LSTM GEMM kernel (compacted learned rows) -----------------
__global__ void __launch_bounds__(256, 2) k_lstmK(
    const float* __restrict__ x, int t, int hpar)
{
    extern __shared__ char smraw[];
    const uint32_t sb = smem_u32(smraw);
    const int tid = threadIdx.x;
    const int w = tid >> 5, lane = tid & 31;
    const int wm = w & 3, wn = w >> 2;

    const int n0 = (blockIdx.x & 15) * 128;
    const int mtile = blockIdx.x >> 4;
    const int cnt = g_cnt[t];
    if (mtile * 128 >= cnt) return;               // uniform early-exit
    const int m0 = mtile * 128;
    const __half* Hh = g_hah[hpar];
    const __half* Hl = g_hal[hpar];
    int* srows = (int*)(smraw + ROWS_OFF);
    float4* sWkp = (float4*)(smraw + EPI_OFF);
    if (tid < 128) {
        srows[tid] = g_rows[t * NB + m0 + tid];
        sWkp[tid] = g_Wkp4[n0 + tid];
    }
    __syncthreads();

    float acc[2][8][4];
#pragma unroll
    for (int i = 0; i < 2; i++)
#pragma unroll
        for (int j = 0; j < 8; j++)
#pragma unroll
            for (int q = 0; q < 4; q++) acc[i][j][q] = 0.f;

    auto load_chunk = [&](int c, int s) {
        const int kc = c * KCH;
        const uint32_t st = sb + s * STAGE_B;
#pragma unroll
        for (int q = 0; q < 2; q++) {
            int i = tid + q * 256;
            int row = i >> 2, seg = i & 3;
            uint32_t so = row * (SROW * 2) + seg * 16;
            int rid = srows[row];
            size_t ar = (size_t)(rid < 0 ? 0 : rid);
            cpasync16(st +              so, Hh + ar * 512 + kc + seg * 8);
            cpasync16(st +     TILE_B + so, Hl + ar * 512 + kc + seg * 8);
            cpasync16(st + 2 * TILE_B + so, g_BLh + (size_t)(n0 + row) * 512 + kc + seg * 8);
            cpasync16(st + 3 * TILE_B + so, g_BLl + (size_t)(n0 + row) * 512 + kc + seg * 8);
        }
    };

    const uint32_t arow = (lane & 15) * (SROW * 2) + ((lane >> 4) << 4);

    auto compute_chunk = [&](int s) {
        const uint32_t st = sb + s * STAGE_B;
#pragma unroll
        for (int ks = 0; ks < 2; ks++) {
            const uint32_t ko = ks * 32;
            uint32_t ah[2][4], al[2][4];
#pragma unroll
            for (int mt = 0; mt < 2; mt++) {
                uint32_t aoff = (wm * 32 + mt * 16) * (SROW * 2) + arow + ko;
                LDSM4(ah[mt][0], ah[mt][1], ah[mt][2], ah[mt][3], st + aoff);
                LDSM4(al[mt][0], al[mt][1], al[mt][2], al[mt][3], st + TILE_B + aoff);
            }
#pragma unroll
            for (int np = 0; np < 4; np++) {
                uint32_t bo = (wn * 64 + np * 16) * (SROW * 2) + arow + ko;
                uint32_t bh[4], bl[4];
                LDSM4(bh[0], bh[1], bh[2], bh[3], st + 2 * TILE_B + bo);
                LDSM4(bl[0], bl[1], bl[2], bl[3], st + 3 * TILE_B + bo);
#pragma unroll
                for (int mt = 0; mt < 2; mt++) {
                    float* ce = acc[mt][np * 2];
                    float* co = acc[mt][np * 2 + 1];
                    mma16816(ce, ah[mt], bh[0], bh[2]);
                    mma16816(ce, ah[mt], bl[0], bl[2]);
                    mma16816(ce, al[mt], bh[0], bh[2]);
                    mma16816(co, ah[mt], bh[1], bh[3]);
                    mma16816(co, ah[mt], bl[1], bl[3]);
                    mma16816(co, al[mt], bh[1], bh[3]);
                }
            }
        }
    };

    load_chunk(0, 0); CP_COMMIT();
    for (int c = 0; c < 16; c++) {
        if (c + 1 < 16) { load_chunk(c + 1, (c + 1) & 1); CP_COMMIT(); CP_WAIT(1); }
        else            { CP_WAIT(0); }
        __syncthreads();
        compute_chunk(c & 1);
        __syncthreads();
    }

    // ---- epilogue: c/tc/oc only ----
    const int grow = lane >> 2, tig = lane & 3;
    const bool evn = (tig & 1) == 0;
    float xs[2][3]; int rid[2]; bool val[2];
#pragma unroll
    for (int mt = 0; mt < 2; mt++) {
        int local = wm * 32 + mt * 16 + grow + (evn ? 0 : 8);
        rid[mt] = srows[local];
        val[mt] = rid[mt] >= 0;
        const float* xp = x + (size_t)(val[mt] ? rid[mt] : 0) * (NT * NF) + t * NF;
        xs[mt][0] = xp[0]; xs[mt][1] = xp[1]; xs[mt][2] = xp[2];
    }
#pragma unroll
    for (int mt = 0; mt < 2; mt++) {
#pragma unroll
        for (int nt = 0; nt < 8; nt++) {
            float* c = acc[mt][nt];
            float p0 = __shfl_xor_sync(0xffffffffu, c[0], 1);
            float p1 = __shfl_xor_sync(0xffffffffu, c[1], 1);
            float p2 = __shfl_xor_sync(0xffffffffu, c[2], 1);
            float p3 = __shfl_xor_sync(0xffffffffu, c[3], 1);
            float zi, zf, zg, zo;
            if (evn) { zi = c[0]; zf = c[1]; zg = p0; zo = p1; }
            else     { zi = p2; zf = p3; zg = c[2]; zo = c[3]; }
            if (!val[mt]) continue;
            int u_loc = wn * 16 + nt * 2 + (tig >> 1);
            float4 w0 = sWkp[u_loc * 4 + 0];
            float4 w1 = sWkp[u_loc * 4 + 1];
            float4 w2 = sWkp[u_loc * 4 + 2];
            float4 w3 = sWkp[u_loc * 4 + 3];
            zi += xs[mt][0]*w0.x + xs[mt][1]*w0.y + xs[mt][2]*w0.z + w0.w;
            zf += xs[mt][0]*w1.x + xs[mt][1]*w1.y + xs[mt][2]*w1.z + w1.w;
            zg += xs[mt][0]*w2.x + xs[mt][1]*w2.y + xs[mt][2]*w2.z + w2.w;
            zo += xs[mt][0]*w3.x + xs[mt][1]*w3.y + xs[mt][2]*w3.z + w3.w;
            int u = (n0 >> 2) + u_loc;
            size_t off = (size_t)rid[mt] * NU + u;
            float ig = sigf(zi), fg = sigf(zf), gg = tanhfast(zg), og = sigf(zo);
            float cold = g_c[off];
            float cn = fmaf(fg, cold, ig * gg);
            g_c[off]  = cn;
            g_tc[off] = tanhfast(cn);
            g_oc[off] = og;
        }
    }
}

// ---------------- combined: gather(tG) blocks + RNN(tR) blocks ---------------
// blocks [0, NG): gather step tG (reads oc/tc from PREVIOUS launch; writes
//                 hah/hal[hpar^1]). If tG < 0, skip (final RNN-only launch).
// blocks [NG, NG+256): RNN step tR (reads hah/hal[hpar] and hph/hpl[par]).
// No cross-group dependency inside this launch -> no sync of any kind.
__global__ void __launch_bounds__(256, 2) k_grnn(
    const float* __restrict__ br, int tR, int tG, int par, int hpar)
{
    const int bid = blockIdx.x;
    const int tid = threadIdx.x;

    if (bid < NG) {
        if (tG < 0) return;
        __half* dh = g_hah[hpar ^ 1];
        __half* dl = g_hal[hpar ^ 1];
        for (int i = bid * 256 + tid; i < NB * 64; i += NG * 256) {
            int b = i >> 6, q = i & 63;
            int src = g_oidx[tG * NB + b];
            const float4* po = (const float4*)(g_oc + (size_t)src * NU) + q * 2;
            const float4* pt = (const float4*)(g_tc + (size_t)b * NU) + q * 2;
            float4 o0 = po[0], o1 = po[1], t0 = pt[0], t1 = pt[1];
            float h[8] = {o0.x*t0.x, o0.y*t0.y, o0.z*t0.z, o0.w*t0.w,
                          o1.x*t1.x, o1.y*t1.y, o1.z*t1.z, o1.w*t1.w};
            uint32_t hw[4], lw[4];
#pragma unroll
            for (int p = 0; p < 4; p++) {
                __half h0, l0, h1, l1;
                split16(h[p*2], h0, l0); split16(h[p*2+1], h1, l1);
                __half2 hh = __halves2half2(h0, h1);
                __half2 ll = __halves2half2(l0, l1);
                hw[p] = *(uint32_t*)&hh; lw[p] = *(uint32_t*)&ll;
            }
            ((uint4*)dh)[i] = make_uint4(hw[0], hw[1], hw[2], hw[3]);
            ((uint4*)dl)[i] = make_uint4(lw[0], lw[1], lw[2], lw[3]);
        }
        return;
    }

    extern __shared__ char smraw[];
    const uint32_t sb = smem_u32(smraw);
    const int w = tid >> 5, lane = tid & 31;
    const int wm = w & 3, wn = w >> 2;

    const int r = bid - NG;
    const int n0 = (r & 3) * 128;
    const int m0 = (r >> 2) * 128;
    const int nch = (tR == 0) ? 16 : 32;
    const __half* Hh = g_hah[hpar];
    const __half* Hl = g_hal[hpar];
    const __half* A2h = g_hph[par];
    const __half* A2l = g_hpl[par];

    float* sbr = (float*)(smraw + EPI_OFF);
    if (tid < 128) sbr[tid] = br[n0 + tid];
    __syncthreads();

    float acc[2][8][4];
#pragma unroll
    for (int i = 0; i < 2; i++)
#pragma unroll
        for (int j = 0; j < 8; j++)
#pragma unroll
            for (int q = 0; q < 4; q++) acc[i][j][q] = 0.f;

    auto load_chunk = [&](int c, int s) {
        const __half *Ah, *Al; int kc;
        if (c < 16) { Ah = Hh;  Al = Hl;  kc = c * KCH; }
        else        { Ah = A2h; Al = A2l; kc = (c - 16) * KCH; }
        const int kb = c * KCH;
        const uint32_t st = sb + s * STAGE_B;
#pragma unroll
        for (int q = 0; q < 2; q++) {
            int i = tid + q * 256;
            int row = i >> 2, seg = i & 3;
            uint32_t so = row * (SROW * 2) + seg * 16;
            size_t ar = (size_t)(m0 + row);
            cpasync16(st +              so, Ah + ar * 512 + kc + seg * 8);
            cpasync16(st +     TILE_B + so, Al + ar * 512 + kc + seg * 8);
            cpasync16(st + 2 * TILE_B + so, g_BRh + (size_t)(n0 + row) * 1024 + kb + seg * 8);
            cpasync16(st + 3 * TILE_B + so, g_BRl + (size_t)(n0 + row) * 1024 + kb + seg * 8);
        }
    };

    const uint32_t arow = (lane & 15) * (SROW * 2) + ((lane >> 4) << 4);

    auto compute_chunk = [&](int s) {
        const uint32_t st = sb + s * STAGE_B;
#pragma unroll
        for (int ks = 0; ks < 2; ks++) {
            const uint32_t ko = ks * 32;
            uint32_t ah[2][4], al[2][4];
#pragma unroll
            for (int mt = 0; mt < 2; mt++) {
                uint32_t aoff = (wm * 32 + mt * 16) * (SROW * 2) + arow + ko;
                LDSM4(ah[mt][0], ah[mt][1], ah[mt][2], ah[mt][3], st + aoff);
                LDSM4(al[mt][0], al[mt][1], al[mt][2], al[mt][3], st + TILE_B + aoff);
            }
#pragma unroll
            for (int np = 0; np < 4; np++) {
                uint32_t bo = (wn * 64 + np * 16) * (SROW * 2) + arow + ko;
                uint32_t bh[4], bl[4];
                LDSM4(bh[0], bh[1], bh[2], bh[3], st + 2 * TILE_B + bo);
                LDSM4(bl[0], bl[1], bl[2], bl[3], st + 3 * TILE_B + bo);
#pragma unroll
                for (int mt = 0; mt < 2; mt++) {
                    float* ce = acc[mt][np * 2];
                    float* co = acc[mt][np * 2 + 1];
                    mma16816(ce, ah[mt], bh[0], bh[2]);
                    mma16816(ce, ah[mt], bl[0], bl[2]);
                    mma16816(ce, al[mt], bh[0], bh[2]);
                    mma16816(co, ah[mt], bh[1], bh[3]);
                    mma16816(co, ah[mt], bl[1], bl[3]);
                    mma16816(co, al[mt], bh[1], bh[3]);
                }
            }
        }
    };

    load_chunk(0, 0); CP_COMMIT();
    for (int c = 0; c < nch; c++) {
        if (c + 1 < nch) { load_chunk(c + 1, (c + 1) & 1); CP_COMMIT(); CP_WAIT(1); }
        else             { CP_WAIT(0); }
        __syncthreads();
        compute_chunk(c & 1);
        __syncthreads();
    }

    // ---- epilogue ----
    const int grow = lane >> 2, tig = lane & 3;
    __half* dh = g_hph[par ^ 1];
    __half* dl = g_hpl[par ^ 1];
    const bool last = (tR == 20);
#pragma unroll
    for (int mt = 0; mt < 2; mt++) {
        int r0 = m0 + wm * 32 + mt * 16 + grow;
#pragma unroll
        for (int nt = 0; nt < 8; nt++) {
            float* c = acc[mt][nt];
            int ncl = wn * 64 + nt * 8 + tig * 2;
            int nc = n0 + ncl;
            float b0 = sbr[ncl], b1 = sbr[ncl + 1];
            float v00 = tanhfast(c[0] + b0), v01 = tanhfast(c[1] + b1);
            float v10 = tanhfast(c[2] + b0), v11 = tanhfast(c[3] + b1);
            if (last) {
                *(float2*)&g_hrf[(size_t)r0 * NU + nc]       = make_float2(v00, v01);
                *(float2*)&g_hrf[(size_t)(r0 + 8) * NU + nc] = make_float2(v10, v11);
            } else {
                __half h0, l0, h1, l1;
                split16(v00, h0, l0); split16(v01, h1, l1);
                *(__half2*)&dh[(size_t)r0 * NU + nc] = __halves2half2(h0, h1);
                *(__half2*)&dl[(size_t)r0 * NU + nc] = __halves2half2(l0, l1);
                split16(v10, h0, l0); split16(v11, h1, l1);
                *(__half2*)&dh[(size_t)(r0 + 8) * NU + nc] = __halves2half2(h0, h1);
                *(__half2*)&dl[(size_t)(r0 + 8) * NU + nc] = __halves2half2(l0, l1);
            }
        }
    }
}

// ---------------- fold FC + final projection --------------------------------
__global__ void k_weff(const float* __restrict__ wfc, const float* __restrict__ bfc,
                       const float* __restrict__ wout, const float* __restrict__ bout)
{
    int k = threadIdx.x;
    float s = 0.f;
#pragma unroll 8
    for (int j = 0; j < 32; j++) s += wfc[k * 32 + j] * wout[j];
    g_weff[k] = s;
    if (k == 0) {
        float b = bout[0];
        for (int j = 0; j < 32; j++) b += bfc[j] * wout[j];
        g_beff = b;
    }
}
__global__ void k_out(float* __restrict__ out) {
    int w = (blockIdx.x * blockDim.x + threadIdx.x) >> 5;
    int lane = threadIdx.x & 31;
    const float* h = g_hrf + (size_t)w * NU;
    float s = 0.f;
#pragma unroll
    for (int q = 0; q < 16; q++) s = fmaf(h[lane + q * 32], g_weff[lane + q * 32], s);
#pragma unroll
    for (int off = 16; off > 0; off >>= 1) s += __shfl_xor_sync(0xffffffffu, s, off);
    if (lane == 0) out[w] = s + g_beff;
}

// ---------------- launcher ---------------------------------------------------
extern "C" void kernel_launch(void* const* d_in, const int* in_sizes, int n_in,
                              void* d_out, int out_size)
{
    const float* x     = (const float*)d_in[0];
    const int*   learn = (const int*)  d_in[1];
    const float* Wk    = (const float*)d_in[2];
    const float* Rk    = (const float*)d_in[3];
    const float* bias  = (const float*)d_in[4];
    const float* Wr    = (const float*)d_in[5];
    const float* Ur    = (const float*)d_in[6];
    const float* br    = (const float*)d_in[7];
    const float* wfc   = (const float*)d_in[8];
    const float* bfc   = (const float*)d_in[9];
    const float* wout  = (const float*)d_in[10];
    const float* bout  = (const float*)d_in[11];
    float* out = (float*)d_out;

    cudaFuncSetAttribute(k_lstmK, cudaFuncAttributeMaxDynamicSharedMemorySize, SM_DYN);
    cudaFuncSetAttribute(k_grnn,  cudaFuncAttributeMaxDynamicSharedMemorySize, SM_DYN);

    k_oidx<<<NT, 1024>>>(learn);
    k_weff<<<1, 512>>>(wfc, bfc, wout, bout);
    k_convRk<<<(NZ * NU) / 256, 256>>>(Rk);
    k_convWU<<<(NU * 1024) / 256, 256>>>(Wr, Ur);
    k_convWkp<<<NZ / 256, 256>>>(Wk, bias);

    // t=0 LSTM: oc/tc/c and h(0) (all rows) into buffer 0
    k_lstm0s<<<(NB * NU) / 256, 256>>>(x);

    for (int t = 0; t < 20; t++) {
        // LSTM(t+1): reads h(t) from hah[t&1], writes c/tc/oc
        k_lstmK<<<1024, 256, SM_DYN>>>(x, t + 1, t & 1);
        // gather(t+1) -> hah[(t+1)&1]  ||  RNN(t) reads hah[t&1], hph[t&1]
        k_grnn<<<NG + 256, 256, SM_DYN>>>(br, t, t + 1, t & 1, t & 1);
    }
    // final RNN t=20: no gather; reads hah[0] (20&1=0), hph[0]
    k_grnn<<<NG + 256, 256, SM_DYN>>>(br, 20, -1, 0, 0);
    k_out<<<NB / 8, 256>>>(out);
}

// round 16
// speedup vs baseline: 1.1794x; 1.1550x over previous
#include <cuda_runtime.h>
#include <cuda_fp16.h>
#include <math.h>
#include <stdint.h>

#define NB 8192
#define NT 21
#define NF 3
#define NU 512
#define NZ 2048

#define KCH 32                    // K per chunk
#define SROW 40                   // smem halves per row (80B, 20 banks -> conflict-free)
#define TILE_B (128 * SROW * 2)   // 10240 B per operand tile
#define STAGE_B (4 * TILE_B)      // Ah/Al/Bh/Bl = 40960 B
#define EPI_OFF (2 * STAGE_B)     // 81920
#define ROWS_OFF (EPI_OFF + 2048) // 83968: int[128] compacted row ids
#define SM_DYN (ROWS_OFF + 640)

#define NRNN 256                  // RNN blocks scheduled first (longest-first)

// ---------------- persistent scratch --------------------------------------
__device__ float  g_c  [NB * NU];
__device__ float  g_tc [NB * NU];
__device__ float  g_oc [NB * NU];
__device__ float  g_hrf[NB * NU];
__device__ __half g_hah[NB * NU];      // LSTM h fp16 hi
__device__ __half g_hal[NB * NU];      // LSTM h fp16 lo (residual)
__device__ __half g_hph[2][NB * NU];   // RNN state hi ping-pong
__device__ __half g_hpl[2][NB * NU];   // RNN state lo ping-pong
__device__ __half g_BLh[NZ * NU];      // permuted lstm weights [n=u*4+g][k] hi
__device__ __half g_BLl[NZ * NU];      // lo
__device__ __half g_BRh[NU * 1024];    // rnn concat [n][k: Wr|Ur] hi
__device__ __half g_BRl[NU * 1024];    // lo
__device__ float4 g_Wkp4[NZ];          // (Wk[0][n],Wk[1][n],Wk[2][n],bias[n]) permuted
__device__ int    g_oidx[NT * NB];
__device__ int    g_rows[NT * NB];     // compacted learned-row ids (padded w/ -1)
__device__ int    g_cnt [NT];
__device__ unsigned char g_m[NT * NB];
__device__ float  g_weff[NU];
__device__ float  g_beff;

// ---------------- helpers ---------------------------------------------------
__device__ __forceinline__ uint32_t smem_u32(const void* p) {
    uint32_t a;
    asm("{ .reg .u64 t; cvta.to.shared.u64 t, %1; cvt.u32.u64 %0, t; }" : "=r"(a) : "l"(p));
    return a;
}
__device__ __forceinline__ void cpasync16(uint32_t dst, const void* src) {
    asm volatile("cp.async.ca.shared.global [%0], [%1], 16;" :: "r"(dst), "l"(src));
}
#define CP_COMMIT() asm volatile("cp.async.commit_group;" ::: "memory")
#define CP_WAIT(n)  asm volatile("cp.async.wait_group %0;" :: "n"(n) : "memory")

#define LDSM4(r0, r1, r2, r3, addr) \
    asm volatile("ldmatrix.sync.aligned.m8n8.x4.shared.b16 {%0,%1,%2,%3}, [%4];" \
        : "=r"(r0), "=r"(r1), "=r"(r2), "=r"(r3) : "r"(addr))

__device__ __forceinline__ void mma16816(float* c, const uint32_t* a, uint32_t b0, uint32_t b1) {
    asm volatile(
        "mma.sync.aligned.m16n8k16.row.col.f32.f16.f16.f32 "
        "{%0,%1,%2,%3}, {%4,%5,%6,%7}, {%8,%9}, {%0,%1,%2,%3};"
        : "+f"(c[0]), "+f"(c[1]), "+f"(c[2]), "+f"(c[3])
        : "r"(a[0]), "r"(a[1]), "r"(a[2]), "r"(a[3]), "r"(b0), "r"(b1));
}
__device__ __forceinline__ float sigf(float z) {
    float e = __expf(-z);
    return __fdividef(1.f, 1.f + e);
}
__device__ __forceinline__ float tanhfast(float z) {
    float e = __expf(fminf(2.f * z, 80.f));
    return __fdividef(e - 1.f, e + 1.f);
}
__device__ __forceinline__ void split16(float f, __half& h, __half& l) {
    h = __float2half_rn(f);
    l = __float2half_rn(f - __half2float(h));
}

// ---------------- mask + cummax gather index + learned-row compaction -------
__global__ void k_oidx(const int* __restrict__ learn) {
    int t = blockIdx.x;
    int tid = threadIdx.x;
    __shared__ int s_any, s_first;
    __shared__ int s_scan[1024];
    if (tid == 0) { s_any = 0; s_first = 0x7fffffff; }
    __syncthreads();
    int base = tid * 8;
    int m[8]; int la = 0;
#pragma unroll
    for (int j = 0; j < 8; j++) { m[j] = (learn[t * NB + base + j] == 1) ? 1 : 0; la |= m[j]; }
    if (la) atomicOr(&s_any, 1);
    __syncthreads();
    if (tid == 0 && !s_any) m[0] = 1;
    int lf = 0x7fffffff;
#pragma unroll
    for (int j = 0; j < 8; j++) if (m[j] && lf == 0x7fffffff) lf = base + j;
    if (lf != 0x7fffffff) atomicMin(&s_first, lf);

    // cummax scan (for o-gather indices)
    int run = -1; int lv[8];
#pragma unroll
    for (int j = 0; j < 8; j++) { if (m[j]) run = base + j; lv[j] = run; }
    s_scan[tid] = run;
    __syncthreads();
    for (int off = 1; off < 1024; off <<= 1) {
        int other = (tid >= off) ? s_scan[tid - off] : -1;
        __syncthreads();
        if (other > s_scan[tid]) s_scan[tid] = other;
        __syncthreads();
    }
    int prefix = (tid > 0) ? s_scan[tid - 1] : -1;
    int first = s_first;
#pragma unroll
    for (int j = 0; j < 8; j++) {
        int v = (lv[j] >= 0) ? lv[j] : prefix;
        g_oidx[t * NB + base + j] = (v < 0) ? first : v;
        g_m[t * NB + base + j] = (unsigned char)m[j];
    }
    __syncthreads();

    // prefix-sum scan -> compacted learned-row list
    int lc = 0;
#pragma unroll
    for (int j = 0; j < 8; j++) lc += m[j];
    s_scan[tid] = lc;
    __syncthreads();
    for (int off = 1; off < 1024; off <<= 1) {
        int other = (tid >= off) ? s_scan[tid - off] : 0;
        __syncthreads();
        s_scan[tid] += other;
        __syncthreads();
    }
    int pos = s_scan[tid] - lc;
    int cnt = s_scan[1023];
#pragma unroll
    for (int j = 0; j < 8; j++) {
        if (m[j]) g_rows[t * NB + pos++] = base + j;
    }
    int padded = (cnt + 127) & ~127;
    int pidx = cnt + tid;
    if (pidx < padded) g_rows[t * NB + pidx] = -1;
    if (tid == 0) g_cnt[t] = cnt;
}

// ---------------- merged setup: weight conversion + FC fold ------------------
// blocks [0,4096):    Rk split -> BLh/BLl (permuted n=u*4+g)
// blocks [4096,6144): Wr|Ur concat split -> BRh/BRl
// blocks [6144,6152): Wk+bias permuted pack -> Wkp4
// blocks [6152,6154): w_eff = w_fc@w_out (+ b_eff)
__global__ void k_setup(
    const float* __restrict__ Rk, const float* __restrict__ Wr,
    const float* __restrict__ Ur, const float* __restrict__ Wk,
    const float* __restrict__ bias,
    const float* __restrict__ wfc, const float* __restrict__ bfc,
    const float* __restrict__ wout, const float* __restrict__ bout)
{
    int b = blockIdx.x, tid = threadIdx.x;
    if (b < 4096) {
        int idx = b * 256 + tid;                  // NZ*NU
        int k = idx & 511, n = idx >> 9;
        float v = Rk[(size_t)k * NZ + (n & 3) * NU + (n >> 2)];
        __half h, l; split16(v, h, l);
        g_BLh[idx] = h; g_BLl[idx] = l;
    } else if (b < 6144) {
        int idx = (b - 4096) * 256 + tid;         // NU*1024
        int k = idx & 1023, n = idx >> 10;
        float v = (k < 512) ? Wr[(size_t)k * NU + n] : Ur[(size_t)(k - 512) * NU + n];
        __half h, l; split16(v, h, l);
        g_BRh[idx] = h; g_BRl[idx] = l;
    } else if (b < 6152) {
        int n = (b - 6144) * 256 + tid;           // NZ
        int col = (n & 3) * NU + (n >> 2);
        g_Wkp4[n] = make_float4(Wk[col], Wk[NZ + col], Wk[2 * NZ + col], bias[col]);
    } else {
        int k = (b - 6152) * 256 + tid;           // NU
        float s = 0.f;
#pragma unroll 8
        for (int j = 0; j < 32; j++) s += wfc[k * 32 + j] * wout[j];
        g_weff[k] = s;
        if (k == 0) {
            float bb = bout[0];
            for (int j = 0; j < 32; j++) bb += bfc[j] * wout[j];
            g_beff = bb;
        }
    }
}

// ---------------- LSTM t=0 (h=0 -> no GEMM); ALSO writes h(0) ---------------
// h(0)[b,u] = oc(0)[oidx_0[b],u]*tc(0)[b,u]: learned b -> oidx=b -> og*tcv;
// unlearned b -> tcv=0 -> 0 = og*tcv. So og*tcv is exact for every row.
__global__ void k_lstm0s(const float* __restrict__ x) {
    int idx = blockIdx.x * 256 + threadIdx.x;     // NB*NU
    int row = idx >> 9, u = idx & 511;
    float x0 = x[row * (NT * NF) + 0];
    float x1 = x[row * (NT * NF) + 1];
    float x2 = x[row * (NT * NF) + 2];
    float4 w0 = g_Wkp4[u * 4 + 0];
    float4 w2 = g_Wkp4[u * 4 + 2];
    float4 w3 = g_Wkp4[u * 4 + 3];
    float zi = x0 * w0.x + x1 * w0.y + x2 * w0.z + w0.w;
    float zg = x0 * w2.x + x1 * w2.y + x2 * w2.z + w2.w;
    float zo = x0 * w3.x + x1 * w3.y + x2 * w3.z + w3.w;
    bool mk = g_m[row] != 0;
    float c = mk ? sigf(zi) * tanhfast(zg) : 0.f;
    float tcv = tanhfast(c);
    float og = sigf(zo);
    g_c[idx] = c;
    g_tc[idx] = tcv;
    g_oc[idx] = og;
    float hv = og * tcv;
    __half hh, hl; split16(hv, hh, hl);
    g_hah[idx] = hh;
    g_hal[idx] = hl;
}

// ---------------- gather: h = oc[oidx]*tc -> fp16 hi/lo ---------------------
__global__ void k_gather(int t) {
    int i = blockIdx.x * 256 + threadIdx.x;       // NB*64
    int b = i >> 6, q = i & 63;
    int src = g_oidx[t * NB + b];
    const float4* po = (const float4*)(g_oc + (size_t)src * NU) + q * 2;
    const float4* pt = (const float4*)(g_tc + (size_t)b * NU) + q * 2;
    float4 o0 = po[0], o1 = po[1], t0 = pt[0], t1 = pt[1];
    float h[8] = {o0.x*t0.x, o0.y*t0.y, o0.z*t0.z, o0.w*t0.w,
                  o1.x*t1.x, o1.y*t1.y, o1.z*t1.z, o1.w*t1.w};
    uint32_t hw[4], lw[4];
#pragma unroll
    for (int p = 0; p < 4; p++) {
        __half h0, l0, h1, l1;
        split16(h[p*2], h0, l0); split16(h[p*2+1], h1, l1);
        __half2 hh = __halves2half2(h0, h1);
        __half2 ll = __halves2half2(l0, l1);
        hw[p] = *(uint32_t*)&hh; lw[p] = *(uint32_t*)&ll;
    }
    ((uint4*)g_hah)[i] = make_uint4(hw[0], hw[1], hw[2], hw[3]);
    ((uint4*)g_hal)[i] = make_uint4(lw[0], lw[1], lw[2], lw[3]);
}

// ---------------- fused HMMA GEMM kernel ------------------------------------
// blocks [0, NRNN): RNN step tR (longest-first).
// blocks [NRNN, ..): LSTM step tL on COMPACTED learned rows (early-exit extras).
__global__ void __launch_bounds__(256, 2) k_hmma(
    const float* __restrict__ x, const float* __restrict__ br,
    int tL, int tR, int par)
{
    extern __shared__ char smraw[];
    const uint32_t sb = smem_u32(smraw);
    const int tid = threadIdx.x;
    const int w = tid >> 5, lane = tid & 31;
    const int wm = w & 3, wn = w >> 2;

    const bool isL = (int)blockIdx.x >= NRNN;
    int m0, n0, nch, t, ldb;
    const __half *Bh, *Bl;
    const __half *A2h = nullptr, *A2l = nullptr;
    int* srows = (int*)(smraw + ROWS_OFF);

    if (isL) {
        int b = blockIdx.x - NRNN;
        n0 = (b & 15) * 128;
        int mtile = b >> 4;
        int cnt = g_cnt[tL];
        if (mtile * 128 >= cnt) return;           // uniform early-exit
        m0 = mtile * 128;
        nch = 16; t = tL; Bh = g_BLh; Bl = g_BLl; ldb = 512;
        if (tid < 128) srows[tid] = g_rows[tL * NB + m0 + tid];
    } else {
        int r = blockIdx.x;
        n0 = (r & 3) * 128; m0 = (r >> 2) * 128;
        nch = (tR == 0) ? 16 : 32; t = tR; Bh = g_BRh; Bl = g_BRl; ldb = 1024;
        A2h = g_hph[par]; A2l = g_hpl[par];
    }

    float4* sWkp = (float4*)(smraw + EPI_OFF);
    float*  sbr  = (float*)(smraw + EPI_OFF);
    if (isL) { if (tid < 128) sWkp[tid] = g_Wkp4[n0 + tid]; }
    else     { if (tid < 128) sbr[tid]  = br[n0 + tid]; }
    __syncthreads();                               // srows/epi visible

    float acc[2][8][4];
#pragma unroll
    for (int i = 0; i < 2; i++)
#pragma unroll
        for (int j = 0; j < 8; j++)
#pragma unroll
            for (int q = 0; q < 4; q++) acc[i][j][q] = 0.f;

    auto load_chunk = [&](int c, int s) {
        const __half *Ah, *Al; int kc;
        if (isL || c < 16) { Ah = g_hah; Al = g_hal; kc = c * KCH; }
        else               { Ah = A2h;   Al = A2l;   kc = (c - 16) * KCH; }
        const int kb = c * KCH;
        const uint32_t st = sb + s * STAGE_B;
#pragma unroll
        for (int q = 0; q < 2; q++) {
            int i = tid + q * 256;
            int row = i >> 2, seg = i & 3;
            uint32_t so = row * (SROW * 2) + seg * 16;
            size_t ar;
            if (isL) { int rid = srows[row]; ar = (size_t)(rid < 0 ? 0 : rid); }
            else     { ar = (size_t)(m0 + row); }
            cpasync16(st +              so, Ah + ar * 512 + kc + seg * 8);
            cpasync16(st +     TILE_B + so, Al + ar * 512 + kc + seg * 8);
            cpasync16(st + 2 * TILE_B + so, Bh + (size_t)(n0 + row) * ldb + kb + seg * 8);
            cpasync16(st + 3 * TILE_B + so, Bl + (size_t)(n0 + row) * ldb + kb + seg * 8);
        }
    };

    const uint32_t arow = (lane & 15) * (SROW * 2) + ((lane >> 4) << 4);

    auto compute_chunk = [&](int s) {
        const uint32_t st = sb + s * STAGE_B;
#pragma unroll
        for (int ks = 0; ks < 2; ks++) {
            const uint32_t ko = ks * 32;             // 16 halves
            uint32_t ah[2][4], al[2][4];
#pragma unroll
            for (int mt = 0; mt < 2; mt++) {
                uint32_t aoff = (wm * 32 + mt * 16) * (SROW * 2) + arow + ko;
                LDSM4(ah[mt][0], ah[mt][1], ah[mt][2], ah[mt][3], st + aoff);
                LDSM4(al[mt][0], al[mt][1], al[mt][2], al[mt][3], st + TILE_B + aoff);
            }
#pragma unroll
            for (int np = 0; np < 4; np++) {
                uint32_t bo = (wn * 64 + np * 16) * (SROW * 2) + arow + ko;
                uint32_t bh[4], bl[4];
                LDSM4(bh[0], bh[1], bh[2], bh[3], st + 2 * TILE_B + bo);
                LDSM4(bl[0], bl[1], bl[2], bl[3], st + 3 * TILE_B + bo);
#pragma unroll
                for (int mt = 0; mt < 2; mt++) {
                    float* ce = acc[mt][np * 2];
                    float* co = acc[mt][np * 2 + 1];
                    mma16816(ce, ah[mt], bh[0], bh[2]);
                    mma16816(ce, ah[mt], bl[0], bl[2]);
                    mma16816(ce, al[mt], bh[0], bh[2]);
                    mma16816(co, ah[mt], bh[1], bh[3]);
                    mma16816(co, ah[mt], bl[1], bl[3]);
                    mma16816(co, al[mt], bh[1], bh[3]);
                }
            }
        }
    };

    load_chunk(0, 0); CP_COMMIT();
    for (int c = 0; c < nch; c++) {
        if (c + 1 < nch) { load_chunk(c + 1, (c + 1) & 1); CP_COMMIT(); CP_WAIT(1); }
        else             { CP_WAIT(0); }
        __syncthreads();
        compute_chunk(c & 1);
        __syncthreads();
    }

    // ---- epilogue ----
    const int grow = lane >> 2, tig = lane & 3;
    const bool evn = (tig & 1) == 0;

    if (isL) {
        float xs[2][3]; int rid[2]; bool val[2];
#pragma unroll
        for (int mt = 0; mt < 2; mt++) {
            int local = wm * 32 + mt * 16 + grow + (evn ? 0 : 8);
            rid[mt] = srows[local];
            val[mt] = rid[mt] >= 0;
            const float* xp = x + (size_t)(val[mt] ? rid[mt] : 0) * (NT * NF) + t * NF;
            xs[mt][0] = xp[0]; xs[mt][1] = xp[1]; xs[mt][2] = xp[2];
        }
#pragma unroll
        for (int mt = 0; mt < 2; mt++) {
#pragma unroll
            for (int nt = 0; nt < 8; nt++) {
                float* c = acc[mt][nt];
                float p0 = __shfl_xor_sync(0xffffffffu, c[0], 1);
                float p1 = __shfl_xor_sync(0xffffffffu, c[1], 1);
                float p2 = __shfl_xor_sync(0xffffffffu, c[2], 1);
                float p3 = __shfl_xor_sync(0xffffffffu, c[3], 1);
                float zi, zf, zg, zo;
                if (evn) { zi = c[0]; zf = c[1]; zg = p0; zo = p1; }
                else     { zi = p2; zf = p3; zg = c[2]; zo = c[3]; }
                if (!val[mt]) continue;
                int u_loc = wn * 16 + nt * 2 + (tig >> 1);
                float4 w0 = sWkp[u_loc * 4 + 0];
                float4 w1 = sWkp[u_loc * 4 + 1];
                float4 w2 = sWkp[u_loc * 4 + 2];
                float4 w3 = sWkp[u_loc * 4 + 3];
                zi += xs[mt][0]*w0.x + xs[mt][1]*w0.y + xs[mt][2]*w0.z + w0.w;
                zf += xs[mt][0]*w1.x + xs[mt][1]*w1.y + xs[mt][2]*w1.z + w1.w;
                zg += xs[mt][0]*w2.x + xs[mt][1]*w2.y + xs[mt][2]*w2.z + w2.w;
                zo += xs[mt][0]*w3.x + xs[mt][1]*w3.y + xs[mt][2]*w3.z + w3.w;
                int u = (n0 >> 2) + u_loc;
                size_t off = (size_t)rid[mt] * NU + u;
                float ig = sigf(zi), fg = sigf(zf), gg = tanhfast(zg), og = sigf(zo);
                float cold = g_c[off];
                float cn = fmaf(fg, cold, ig * gg);    // all listed rows are learned
                g_c[off]  = cn;
                g_tc[off] = tanhfast(cn);
                g_oc[off] = og;
            }
        }
    } else {
        __half* dh = g_hph[par ^ 1];
        __half* dl = g_hpl[par ^ 1];
        const bool last = (tR == 20);
#pragma unroll
        for (int mt = 0; mt < 2; mt++) {
            int r0 = m0 + wm * 32 + mt * 16 + grow;
#pragma unroll
            for (int nt = 0; nt < 8; nt++) {
                float* c = acc[mt][nt];
                int ncl = wn * 64 + nt * 8 + tig * 2;
                int nc = n0 + ncl;
                float b0 = sbr[ncl], b1 = sbr[ncl + 1];
                float v00 = tanhfast(c[0] + b0), v01 = tanhfast(c[1] + b1);
                float v10 = tanhfast(c[2] + b0), v11 = tanhfast(c[3] + b1);
                if (last) {
                    *(float2*)&g_hrf[(size_t)r0 * NU + nc]       = make_float2(v00, v01);
                    *(float2*)&g_hrf[(size_t)(r0 + 8) * NU + nc] = make_float2(v10, v11);
                } else {
                    __half h0, l0, h1, l1;
                    split16(v00, h0, l0); split16(v01, h1, l1);
                    *(__half2*)&dh[(size_t)r0 * NU + nc] = __halves2half2(h0, h1);
                    *(__half2*)&dl[(size_t)r0 * NU + nc] = __halves2half2(l0, l1);
                    split16(v10, h0, l0); split16(v11, h1, l1);
                    *(__half2*)&dh[(size_t)(r0 + 8) * NU + nc] = __halves2half2(h0, h1);
                    *(__half2*)&dl[(size_t)(r0 + 8) * NU + nc] = __halves2half2(l0, l1);
                }
            }
        }
    }
}

// ---------------- final projection ------------------------------------------
__global__ void k_out(float* __restrict__ out) {
    int w = (blockIdx.x * blockDim.x + threadIdx.x) >> 5;
    int lane = threadIdx.x & 31;
    const float* h = g_hrf + (size_t)w * NU;
    float s = 0.f;
#pragma unroll
    for (int q = 0; q < 16; q++) s = fmaf(h[lane + q * 32], g_weff[lane + q * 32], s);
#pragma unroll
    for (int off = 16; off > 0; off >>= 1) s += __shfl_xor_sync(0xffffffffu, s, off);
    if (lane == 0) out[w] = s + g_beff;
}

// ---------------- launcher ---------------------------------------------------
extern "C" void kernel_launch(void* const* d_in, const int* in_sizes, int n_in,
                              void* d_out, int out_size)
{
    const float* x     = (const float*)d_in[0];
    const int*   learn = (const int*)  d_in[1];
    const float* Wk    = (const float*)d_in[2];
    const float* Rk    = (const float*)d_in[3];
    const float* bias  = (const float*)d_in[4];
    const float* Wr    = (const float*)d_in[5];
    const float* Ur    = (const float*)d_in[6];
    const float* br    = (const float*)d_in[7];
    const float* wfc   = (const float*)d_in[8];
    const float* bfc   = (const float*)d_in[9];
    const float* wout  = (const float*)d_in[10];
    const float* bout  = (const float*)d_in[11];
    float* out = (float*)d_out;

    cudaFuncSetAttribute(k_hmma, cudaFuncAttributeMaxDynamicSharedMemorySize, SM_DYN);

    k_oidx<<<NT, 1024>>>(learn);
    k_setup<<<6154, 256>>>(Rk, Wr, Ur, Wk, bias, wfc, bfc, wout, bout);

    // t=0 LSTM: oc/tc/c AND h(0) for all rows (gather(0) folded in)
    k_lstm0s<<<(NB * NU) / 256, 256>>>(x);

    for (int t = 0; t < 20; t++) {
        // RNN(t) blocks first (longest), then compacted-LSTM(t+1) blocks
        k_hmma<<<NRNN + 1024, 256, SM_DYN>>>(x, br, t + 1, t, t & 1);
        k_gather<<<(NB * 64) / 256, 256>>>(t + 1);
    }
    // final RNN t=20 (t=19 wrote hph[(19&1)^1] = hph[0] -> par=0)
    k_hmma<<<NRNN, 256, SM_DYN>>>(x, br, -1, 20, 0);
    k_out<<<NB / 8, 256>>>(out);
}